// round 16
// baseline (speedup 1.0000x reference)
#include <cuda_runtime.h>
#include <cuda_fp16.h>
#include <math.h>

#define HID 4096
#define SEQ 2048
#define NH 32
#define HD 128

typedef unsigned int u32;

// Static scratch (no cudaMalloc allowed)
__device__ __align__(256) __half g_Xh[SEQ * HID];
__device__ __align__(256) __half g_Wq[HID * HID];
__device__ __align__(256) __half g_Wk[HID * HID];
__device__ __align__(256) __half g_Wv[HID * HID];
__device__ __align__(256) __half g_Wo[HID * HID];
__device__ __align__(256) __half g_Qh[SEQ * HID];
__device__ __align__(256) __half g_Kh[SEQ * HID];
__device__ __align__(256) __half g_Vh[SEQ * HID];
__device__ __align__(256) __half g_Ah[SEQ * HID];

#define NPERSIST 296                          // 148 SMs x 2 CTAs

__device__ __forceinline__ u32 smem_u32(const void* p) {
    u32 a;
    asm("{ .reg .u64 t; cvta.to.shared.u64 t, %1; cvt.u32.u64 %0, t; }"
        : "=r"(a) : "l"(p));
    return a;
}
__device__ __forceinline__ void cp16(u32 dst, const void* src) {
    asm volatile("cp.async.cg.shared.global [%0], [%1], 16;\n" :: "r"(dst), "l"(src));
}
__device__ __forceinline__ void ldmx4(u32 addr, u32& r0, u32& r1, u32& r2, u32& r3) {
    asm volatile("ldmatrix.sync.aligned.m8n8.x4.shared.b16 {%0,%1,%2,%3}, [%4];"
                 : "=r"(r0), "=r"(r1), "=r"(r2), "=r"(r3) : "r"(addr));
}
__device__ __forceinline__ void ldmx4t(u32 addr, u32& r0, u32& r1, u32& r2, u32& r3) {
    asm volatile("ldmatrix.sync.aligned.m8n8.x4.trans.shared.b16 {%0,%1,%2,%3}, [%4];"
                 : "=r"(r0), "=r"(r1), "=r"(r2), "=r"(r3) : "r"(addr));
}
__device__ __forceinline__ void mma_h(float* c, const u32* a, const u32* b) {
    asm volatile(
        "mma.sync.aligned.m16n8k16.row.col.f32.f16.f16.f32 "
        "{%0,%1,%2,%3}, {%4,%5,%6,%7}, {%8,%9}, {%0,%1,%2,%3};"
        : "+f"(c[0]), "+f"(c[1]), "+f"(c[2]), "+f"(c[3])
        : "r"(a[0]), "r"(a[1]), "r"(a[2]), "r"(a[3]), "r"(b[0]), "r"(b[1]));
}
__device__ __forceinline__ u32 pack_h2(float a, float b) {
    __half2 h = __floats2half2_rn(a, b);
    return *reinterpret_cast<u32*>(&h);
}

// ---------------------------------------------------------------------------
// fp32 -> fp16 converts, single launch: grid.y 0..3 = weights, 4 = x.
// ---------------------------------------------------------------------------
__device__ __forceinline__ void cvt_one(const float4* __restrict__ src,
                                        uint4* __restrict__ dst, int n8, int i) {
    if (i < n8) {
        float4 v = src[2 * i];
        float4 w = src[2 * i + 1];
        uint4 o;
        o.x = pack_h2(v.x, v.y);
        o.y = pack_h2(v.z, v.w);
        o.z = pack_h2(w.x, w.y);
        o.w = pack_h2(w.z, w.w);
        dst[i] = o;
    }
}

__global__ void cvt_all(const float4* __restrict__ s0, const float4* __restrict__ s1,
                        const float4* __restrict__ s2, const float4* __restrict__ s3,
                        const float4* __restrict__ sx, int nw8, int nx8) {
    int z = blockIdx.y;
    const float4* src = (z == 0) ? s0 : (z == 1) ? s1 : (z == 2) ? s2
                      : (z == 3) ? s3 : sx;
    uint4* dst = (z == 0) ? (uint4*)g_Wq : (z == 1) ? (uint4*)g_Wk
               : (z == 2) ? (uint4*)g_Wv : (z == 3) ? (uint4*)g_Wo : (uint4*)g_Xh;
    int n8 = (z == 4) ? nx8 : nw8;
    int i = (blockIdx.x * blockDim.x + threadIdx.x) * 2;
    cvt_one(src, dst, n8, i);
    cvt_one(src, dst, n8, i + 1);
}

// ===========================================================================
// fp16 mma GEMM (NT): BM=BN=128, BK=64, 8 warps (2x4), warp tile 64x32,
// 3-stage cp.async ring, one __syncthreads per K-iter, 2 CTAs/SM.
// ===========================================================================
#define ROWB 144
#define GTILE (128 * ROWB)
#define GSTG  (2 * GTILE)                     // 36864 per stage
#define GEMM_SMEM (3 * GSTG)                  // 110592 (x2 CTAs = 216KB)

__device__ __forceinline__ void gemm_stage_load(
    const __half* __restrict__ A, const __half* __restrict__ Bw, int K,
    int bm, int bn, int k0, u32 sA, u32 sB, int tid)
{
#pragma unroll
    for (int i = 0; i < 4; i++) {
        int c = tid + i * 256;
        int r = c >> 3, cb = (c & 7) << 4;
        cp16(sA + r * ROWB + cb,
             (const char*)(A + (long)(bm + r) * K + k0) + cb);
    }
#pragma unroll
    for (int i = 0; i < 4; i++) {
        int c = tid + i * 256;
        int r = c >> 3, cb = (c & 7) << 4;
        cp16(sB + r * ROWB + cb,
             (const char*)(Bw + (long)(bn + r) * K + k0) + cb);
    }
}

// One K-iteration of compute on a given stage slot.
__device__ __forceinline__ void gemm_compute_iter(
    u32 slotbase, u32 a_off, u32 b_off, float acc[4][4][4])
{
    u32 aB = slotbase + a_off;
    u32 bB = slotbase + GTILE + b_off;
#pragma unroll
    for (int ks = 0; ks < 4; ks++) {
        u32 af[4][4], bf[2][4];
#pragma unroll
        for (int mt = 0; mt < 4; mt++)
            ldmx4(aB + mt * (16 * ROWB) + ks * 32,
                  af[mt][0], af[mt][1], af[mt][2], af[mt][3]);
#pragma unroll
        for (int np = 0; np < 2; np++)
            ldmx4(bB + np * (64 * ROWB) + ks * 32,
                  bf[np][0], bf[np][1], bf[np][2], bf[np][3]);
#pragma unroll
        for (int mt = 0; mt < 4; mt++)
#pragma unroll
            for (int nt = 0; nt < 4; nt++)
                mma_h(acc[mt][nt], af[mt], &bf[nt >> 1][(nt & 1) * 2]);
    }
}

__device__ __forceinline__ void gemm_core(
    const __half* __restrict__ A, const __half* __restrict__ Bw,
    int bm, int bn, int K, u32 sbase, int tid,
    u32 a_off, u32 b_off, float acc[4][4][4])
{
    const int KT = K / 64;

    gemm_stage_load(A, Bw, K, bm, bn, 0, sbase, sbase + GTILE, tid);
    asm volatile("cp.async.commit_group;\n" ::: "memory");
    gemm_stage_load(A, Bw, K, bm, bn, 64, sbase + GSTG, sbase + GSTG + GTILE, tid);
    asm volatile("cp.async.commit_group;\n" ::: "memory");

    int slot = 0;
    for (int kt = 0; kt < KT; kt++) {
        asm volatile("cp.async.wait_group %0;\n" :: "n"(1) : "memory");
        __syncthreads();

        if (kt + 2 < KT) {
            int ps = slot + 2;
            if (ps >= 3) ps -= 3;
            u32 st = sbase + ps * GSTG;
            gemm_stage_load(A, Bw, K, bm, bn, (kt + 2) * 64, st, st + GTILE, tid);
        }
        asm volatile("cp.async.commit_group;\n" ::: "memory");

        gemm_compute_iter(sbase + slot * GSTG, a_off, b_off, acc);
        if (++slot == 3) slot = 0;
    }
}

// ---------------------------------------------------------------------------
// Stream-persistent fused Q/K/V projection. Each CTA owns tiles
// t = bid + i*296 (t in [0,1536)); the 3-stage cp.async ring cycles
// CONTINUOUSLY across tile boundaries (no per-tile drain). Epilogue for a
// finished tile runs from registers while the next tile's loads are in
// flight. z = t/512 selects weight/output; z<2 applies RoPE.
// ---------------------------------------------------------------------------
__global__ __launch_bounds__(256, 2) void gemm_qkv(const __half* __restrict__ A,
                                                   const int* __restrict__ pos) {
    extern __shared__ char smg[];
    u32 sbase = smem_u32(smg);
    int tid = threadIdx.x;
    int lane = tid & 31, wid = tid >> 5;
    int wm = wid & 1, wn = wid >> 1;
    int bid = blockIdx.x;

    u32 a_off = (u32)((wm * 64 + (lane & 15)) * ROWB + (lane >> 4) * 16);
    u32 b_off = (u32)((wn * 16 + (lane & 7) + ((lane & 16) ? 8 : 0)) * ROWB +
                      ((lane & 8) ? 16 : 0));

    int nMine = (1536 - bid + NPERSIST - 1) / NPERSIST;
    if (nMine <= 0) return;
    long nIt = (long)nMine * 64;

    // stage loader for linear iteration j (tile index j/64, kt j%64)
    auto load_it = [&](long j) {
        int ti = (int)(j >> 6);
        int kt = (int)(j & 63);
        int t = bid + ti * NPERSIST;
        int z = t >> 9;
        int rem = t & 511;
        int by = rem >> 5, bx = rem & 31;
        const __half* Bw = (z == 0) ? g_Wq : (z == 1) ? g_Wk : g_Wv;
        u32 st = sbase + (u32)(j % 3) * GSTG;
        gemm_stage_load(A, Bw, HID, by * 128, bx * 128, kt * 64,
                        st, st + GTILE, tid);
    };

    load_it(0);
    asm volatile("cp.async.commit_group;\n" ::: "memory");
    if (nIt > 1) load_it(1);
    asm volatile("cp.async.commit_group;\n" ::: "memory");

    float acc[4][4][4];
#pragma unroll
    for (int i = 0; i < 4; i++)
#pragma unroll
        for (int jj = 0; jj < 4; jj++)
#pragma unroll
            for (int q = 0; q < 4; q++) acc[i][jj][q] = 0.f;

    for (long j = 0; j < nIt; j++) {
        asm volatile("cp.async.wait_group %0;\n" :: "n"(1) : "memory");
        __syncthreads();

        if (j + 2 < nIt) load_it(j + 2);
        asm volatile("cp.async.commit_group;\n" ::: "memory");

        gemm_compute_iter(sbase + (u32)(j % 3) * GSTG, a_off, b_off, acc);

        if ((j & 63) == 63) {
            // tile finished: epilogue from registers (no smem use).
            int t = bid + (int)(j >> 6) * NPERSIST;
            int z = t >> 9;
            int rem = t & 511;
            int by = rem >> 5, bx = rem & 31;
            int bm = by * 128, bn = bx * 128;
            __half* C = (z == 0) ? g_Qh : (z == 1) ? g_Kh : g_Vh;

            int r0 = bm + wm * 64 + (lane >> 2);
            int cq0 = wn * 16 + (lane & 3) * 2;

            if (z < 2) {
                int rh = NH - 1 - bx;          // reversed head order
                float ratio_inv = 1.0f / (1.0f + 2.0f * ((float)rh / (float)NH));
                const float L2 = 13.287712379549449f;
#pragma unroll
                for (int mt = 0; mt < 4; mt++) {
#pragma unroll
                    for (int tt = 0; tt < 2; tt++) {
                        int row = r0 + mt * 16 + tt * 8;
                        float tp = (float)pos[row] * ratio_inv;
#pragma unroll
                        for (int loc = 0; loc < 2; loc++) {
#pragma unroll
                            for (int cq = 0; cq < 2; cq++) {
                                int d = cq0 + loc * 8 + cq;
                                float inv_freq =
                                    exp2f(-((float)d * (1.0f / 64.0f)) * L2);
                                float sn, cs;
                                sincosf(tp * inv_freq, &sn, &cs);
                                int q = tt * 2 + cq;
                                float a = acc[mt][loc][q];
                                float b = acc[mt][loc + 2][q];
                                acc[mt][loc][q]     = a * cs - b * sn;
                                acc[mt][loc + 2][q] = b * cs + a * sn;
                            }
                        }
                    }
                }
            }

#pragma unroll
            for (int mt = 0; mt < 4; mt++) {
#pragma unroll
                for (int nt = 0; nt < 4; nt++) {
                    long r = r0 + mt * 16;
                    int c = bn + cq0 + (nt & 1) * 8 + (nt >> 1) * 64;
                    *(u32*)((char*)C + (r * HID + c) * 2) =
                        pack_h2(acc[mt][nt][0], acc[mt][nt][1]);
                    *(u32*)((char*)C + ((r + 8) * HID + c) * 2) =
                        pack_h2(acc[mt][nt][2], acc[mt][nt][3]);
                }
            }

#pragma unroll
            for (int i = 0; i < 4; i++)
#pragma unroll
                for (int jj = 0; jj < 4; jj++)
#pragma unroll
                    for (int q = 0; q < 4; q++) acc[i][jj][q] = 0.f;
        }
    }
}

// Output projection: fp32 out (plain non-persistent launch).
__global__ __launch_bounds__(256, 2) void gemm_o(const __half* __restrict__ A,
                                                 float* __restrict__ C) {
    extern __shared__ char smg[];
    u32 sbase = smem_u32(smg);
    int tid = threadIdx.x;
    int lane = tid & 31, wid = tid >> 5;
    int wm = wid & 1, wn = wid >> 1;
    int bm = blockIdx.y * 128;
    int bn = blockIdx.x * 128;

    u32 a_off = (u32)((wm * 64 + (lane & 15)) * ROWB + (lane >> 4) * 16);
    u32 b_off = (u32)((wn * 16 + (lane & 7) + ((lane & 16) ? 8 : 0)) * ROWB +
                      ((lane & 8) ? 16 : 0));

    float acc[4][4][4];
#pragma unroll
    for (int i = 0; i < 4; i++)
#pragma unroll
        for (int j = 0; j < 4; j++)
#pragma unroll
            for (int q = 0; q < 4; q++) acc[i][j][q] = 0.f;

    gemm_core(A, g_Wo, bm, bn, HID, sbase, tid, a_off, b_off, acc);

    int r0 = bm + wm * 64 + (lane >> 2);
    int cq0 = wn * 16 + (lane & 3) * 2;
#pragma unroll
    for (int mt = 0; mt < 4; mt++) {
#pragma unroll
        for (int nt = 0; nt < 4; nt++) {
            long r = r0 + mt * 16;
            int c = bn + cq0 + (nt & 1) * 8 + (nt >> 1) * 64;
            *(float2*)&C[r * HID + c] =
                make_float2(acc[mt][nt][0], acc[mt][nt][1]);
            *(float2*)&C[(r + 8) * HID + c] =
                make_float2(acc[mt][nt][2], acc[mt][nt][3]);
        }
    }
}

// ===========================================================================
// fp16 tensor-core causal flash attention. BQ=64, BKV=64, D=128, 128 thr,
// 3 CTAs/SM, Q fragments from global, grid (head, tile) big-first.
// ===========================================================================
#define FROWB 272
#define FTILE (64 * FROWB)                     // 17408
#define FSTG (2 * FTILE)                       // K + V per stage
#define FLASH_SMEM (2 * FSTG)                  // 69632 (x3 CTAs = 209KB)

__global__ __launch_bounds__(128, 3) void flash_h() {
    extern __shared__ char smf[];
    u32 sbase = smem_u32(smf);
    int tid = threadIdx.x;
    int lane = tid & 31, wid = tid >> 5;       // 4 warps
    int h = blockIdx.x;                        // head (x-fastest)
    int qt = 31 - blockIdx.y;                  // big tiles first across heads
    int q0 = qt * 64;
    int nk = qt + 1;

    // KV stage 0
    {
        u32 kb = sbase, vb = sbase + FTILE;
#pragma unroll
        for (int i = 0; i < 8; i++) {
            int c = tid + i * 128;
            int r = c >> 4, cb = (c & 15) << 4;
            long gb = (long)r * HID + h * HD;
            cp16(kb + r * FROWB + cb, (const char*)(g_Kh + gb) + cb);
            cp16(vb + r * FROWB + cb, (const char*)(g_Vh + gb) + cb);
        }
    }
    asm volatile("cp.async.commit_group;\n" ::: "memory");

    // Q fragments straight from global in mma A layout.
    u32 aq[8][4];
    {
        const __half* qb = g_Qh + (long)(q0 + wid * 16 + (lane >> 2)) * HID
                         + h * HD + (lane & 3) * 2;
#pragma unroll
        for (int d8 = 0; d8 < 8; d8++)
#pragma unroll
            for (int j = 0; j < 4; j++)
                aq[d8][j] = *(const u32*)(qb + (long)(j & 1) * 8 * HID
                                             + d8 * 16 + (j >> 1) * 8);
    }

    float o[16][4];
    float m[2] = {-INFINITY, -INFINITY};
    float l[2] = {0.f, 0.f};
#pragma unroll
    for (int nt = 0; nt < 16; nt++)
#pragma unroll
        for (int q = 0; q < 4; q++) o[nt][q] = 0.f;

    const float SC = 0.1275174461600732f;      // 1/sqrt(128) * log2(e)
    u32 k_off = (u32)(((lane & 7) + ((lane & 16) ? 8 : 0)) * FROWB +
                      ((lane & 8) ? 16 : 0));
    u32 v_off = (u32)(((lane & 7) + ((lane & 8) ? 8 : 0)) * FROWB +
                      ((lane & 16) ? 16 : 0));

    for (int kt = 0; kt < nk; kt++) {
        int k0 = kt * 64;
        asm volatile("cp.async.wait_group 0;\n" ::: "memory");
        __syncthreads();

        if (kt + 1 < nk) {
            u32 kb = sbase + ((kt + 1) & 1) * FSTG;
            u32 vb = kb + FTILE;
            long krow = (long)(kt + 1) * 64;
#pragma unroll
            for (int i = 0; i < 8; i++) {
                int c = tid + i * 128;
                int r = c >> 4, cb = (c & 15) << 4;
                long gb = (krow + r) * HID + h * HD;
                cp16(kb + r * FROWB + cb, (const char*)(g_Kh + gb) + cb);
                cp16(vb + r * FROWB + cb, (const char*)(g_Vh + gb) + cb);
            }
            asm volatile("cp.async.commit_group;\n" ::: "memory");
        }

        u32 kbase = sbase + (kt & 1) * FSTG;
        u32 vbase = kbase + FTILE;

        float c[8][4];
#pragma unroll
        for (int j = 0; j < 8; j++)
#pragma unroll
            for (int q = 0; q < 4; q++) c[j][q] = 0.f;

#pragma unroll
        for (int d8 = 0; d8 < 8; d8++) {
            u32 bf[4][4];
#pragma unroll
            for (int np = 0; np < 4; np++)
                ldmx4(kbase + k_off + np * (16 * FROWB) + d8 * 32,
                      bf[np][0], bf[np][1], bf[np][2], bf[np][3]);
#pragma unroll
            for (int np = 0; np < 4; np++) {
                mma_h(c[2 * np],     aq[d8], &bf[np][0]);
                mma_h(c[2 * np + 1], aq[d8], &bf[np][2]);
            }
        }

#pragma unroll
        for (int j = 0; j < 8; j++)
#pragma unroll
            for (int q = 0; q < 4; q++) c[j][q] *= SC;

        if (k0 + 63 > q0 + wid * 16) {
            int rbase = q0 + wid * 16 + (lane >> 2);
#pragma unroll
            for (int j = 0; j < 8; j++) {
                int col = k0 + j * 8 + (lane & 3) * 2;
#pragma unroll
                for (int t = 0; t < 2; t++) {
                    int row = rbase + t * 8;
                    if (col > row)     c[j][2 * t]     = -INFINITY;
                    if (col + 1 > row) c[j][2 * t + 1] = -INFINITY;
                }
            }
        }

#pragma unroll
        for (int t = 0; t < 2; t++) {
            float mx = -INFINITY;
#pragma unroll
            for (int j = 0; j < 8; j++)
                mx = fmaxf(mx, fmaxf(c[j][2 * t], c[j][2 * t + 1]));
            mx = fmaxf(mx, __shfl_xor_sync(0xffffffffu, mx, 1));
            mx = fmaxf(mx, __shfl_xor_sync(0xffffffffu, mx, 2));
            float mnew = fmaxf(m[t], mx);
            float corr = exp2f(m[t] - mnew);
            float rs = 0.f;
#pragma unroll
            for (int j = 0; j < 8; j++) {
                float p0 = exp2f(c[j][2 * t] - mnew);
                float p1 = exp2f(c[j][2 * t + 1] - mnew);
                c[j][2 * t] = p0;
                c[j][2 * t + 1] = p1;
                rs += p0 + p1;
            }
            rs += __shfl_xor_sync(0xffffffffu, rs, 1);
            rs += __shfl_xor_sync(0xffffffffu, rs, 2);
            l[t] = l[t] * corr + rs;
            m[t] = mnew;
#pragma unroll
            for (int nt = 0; nt < 16; nt++) {
                o[nt][2 * t] *= corr;
                o[nt][2 * t + 1] *= corr;
            }
        }

        u32 ph[4][4];
#pragma unroll
        for (int t = 0; t < 4; t++) {
            ph[t][0] = pack_h2(c[2 * t][0], c[2 * t][1]);
            ph[t][1] = pack_h2(c[2 * t][2], c[2 * t][3]);
            ph[t][2] = pack_h2(c[2 * t + 1][0], c[2 * t + 1][1]);
            ph[t][3] = pack_h2(c[2 * t + 1][2], c[2 * t + 1][3]);
        }

#pragma unroll
        for (int t = 0; t < 4; t++) {
            u32 vrow = vbase + v_off + t * (16 * FROWB);
#pragma unroll
            for (int np = 0; np < 8; np++) {
                u32 b0, b1, b2, b3;
                ldmx4t(vrow + np * 32, b0, b1, b2, b3);
                u32 bl[2] = {b0, b1};
                u32 bh[2] = {b2, b3};
                mma_h(o[2 * np], ph[t], bl);
                mma_h(o[2 * np + 1], ph[t], bh);
            }
        }
    }

    float inv0 = 1.0f / l[0], inv1 = 1.0f / l[1];
    long row = q0 + wid * 16 + (lane >> 2);
    int colb = h * HD + (lane & 3) * 2;
#pragma unroll
    for (int nt = 0; nt < 16; nt++) {
        int c = colb + nt * 8;
        *(u32*)((char*)g_Ah + (row * HID + c) * 2) =
            pack_h2(o[nt][0] * inv0, o[nt][1] * inv0);
        *(u32*)((char*)g_Ah + ((row + 8) * HID + c) * 2) =
            pack_h2(o[nt][2] * inv1, o[nt][3] * inv1);
    }
}

// ---------------------------------------------------------------------------
extern "C" void kernel_launch(void* const* d_in, const int* in_sizes, int n_in,
                              void* d_out, int out_size) {
    (void)in_sizes; (void)n_in; (void)out_size;
    const float* x   = (const float*)d_in[0];
    const int*   pos = (const int*)d_in[1];
    const float* wq  = (const float*)d_in[2];
    const float* wk  = (const float*)d_in[3];
    const float* wv  = (const float*)d_in[4];
    const float* wo  = (const float*)d_in[5];
    float* out = (float*)d_out;

    __half *Xh, *Ah;
    cudaGetSymbolAddress((void**)&Xh, g_Xh);
    cudaGetSymbolAddress((void**)&Ah, g_Ah);

    {
        int nx8 = SEQ * HID / 8;
        int nw8 = HID * HID / 8;
        int bw = (nw8 / 2 + 255) / 256;
        cvt_all<<<dim3(bw, 5), 256>>>((const float4*)wq, (const float4*)wk,
                                      (const float4*)wv, (const float4*)wo,
                                      (const float4*)x, nw8, nx8);
    }

    cudaFuncSetAttribute(gemm_qkv,
                         cudaFuncAttributeMaxDynamicSharedMemorySize, GEMM_SMEM);
    cudaFuncSetAttribute(gemm_o,
                         cudaFuncAttributeMaxDynamicSharedMemorySize, GEMM_SMEM);
    cudaFuncSetAttribute(flash_h,
                         cudaFuncAttributeMaxDynamicSharedMemorySize, FLASH_SMEM);

    gemm_qkv<<<NPERSIST, 256, GEMM_SMEM>>>(Xh, pos);

    flash_h<<<dim3(32, 32), 128, FLASH_SMEM>>>();

    gemm_o<<<dim3(32, 16), 256, GEMM_SMEM>>>(Ah, out);
}

// round 17
// speedup vs baseline: 1.0736x; 1.0736x over previous
#include <cuda_runtime.h>
#include <cuda_fp16.h>
#include <math.h>

#define HID 4096
#define SEQ 2048
#define NH 32
#define HD 128

typedef unsigned int u32;

// Static scratch (no cudaMalloc allowed)
__device__ __align__(256) __half g_Xh[SEQ * HID];
__device__ __align__(256) __half g_Wq[HID * HID];
__device__ __align__(256) __half g_Wk[HID * HID];
__device__ __align__(256) __half g_Wv[HID * HID];
__device__ __align__(256) __half g_Wo[HID * HID];
__device__ __align__(256) __half g_Qh[SEQ * HID];
__device__ __align__(256) __half g_Kh[SEQ * HID];
__device__ __align__(256) __half g_Vh[SEQ * HID];
__device__ __align__(256) __half g_Ah[SEQ * HID];

__device__ __forceinline__ u32 smem_u32(const void* p) {
    u32 a;
    asm("{ .reg .u64 t; cvta.to.shared.u64 t, %1; cvt.u32.u64 %0, t; }"
        : "=r"(a) : "l"(p));
    return a;
}
__device__ __forceinline__ void cp16(u32 dst, const void* src) {
    asm volatile("cp.async.cg.shared.global [%0], [%1], 16;\n" :: "r"(dst), "l"(src));
}
__device__ __forceinline__ void ldmx4(u32 addr, u32& r0, u32& r1, u32& r2, u32& r3) {
    asm volatile("ldmatrix.sync.aligned.m8n8.x4.shared.b16 {%0,%1,%2,%3}, [%4];"
                 : "=r"(r0), "=r"(r1), "=r"(r2), "=r"(r3) : "r"(addr));
}
__device__ __forceinline__ void ldmx4t(u32 addr, u32& r0, u32& r1, u32& r2, u32& r3) {
    asm volatile("ldmatrix.sync.aligned.m8n8.x4.trans.shared.b16 {%0,%1,%2,%3}, [%4];"
                 : "=r"(r0), "=r"(r1), "=r"(r2), "=r"(r3) : "r"(addr));
}
__device__ __forceinline__ void mma_h(float* c, const u32* a, const u32* b) {
    asm volatile(
        "mma.sync.aligned.m16n8k16.row.col.f32.f16.f16.f32 "
        "{%0,%1,%2,%3}, {%4,%5,%6,%7}, {%8,%9}, {%0,%1,%2,%3};"
        : "+f"(c[0]), "+f"(c[1]), "+f"(c[2]), "+f"(c[3])
        : "r"(a[0]), "r"(a[1]), "r"(a[2]), "r"(a[3]), "r"(b[0]), "r"(b[1]));
}
__device__ __forceinline__ u32 pack_h2(float a, float b) {
    __half2 h = __floats2half2_rn(a, b);
    return *reinterpret_cast<u32*>(&h);
}

// ---------------------------------------------------------------------------
// fp32 -> fp16 converts, single launch: grid.y 0..3 = weights, 4 = x.
// ---------------------------------------------------------------------------
__device__ __forceinline__ void cvt_one(const float4* __restrict__ src,
                                        uint4* __restrict__ dst, int n8, int i) {
    if (i < n8) {
        float4 v = src[2 * i];
        float4 w = src[2 * i + 1];
        uint4 o;
        o.x = pack_h2(v.x, v.y);
        o.y = pack_h2(v.z, v.w);
        o.z = pack_h2(w.x, w.y);
        o.w = pack_h2(w.z, w.w);
        dst[i] = o;
    }
}

__global__ void cvt_all(const float4* __restrict__ s0, const float4* __restrict__ s1,
                        const float4* __restrict__ s2, const float4* __restrict__ s3,
                        const float4* __restrict__ sx, int nw8, int nx8) {
    int z = blockIdx.y;
    const float4* src = (z == 0) ? s0 : (z == 1) ? s1 : (z == 2) ? s2
                      : (z == 3) ? s3 : sx;
    uint4* dst = (z == 0) ? (uint4*)g_Wq : (z == 1) ? (uint4*)g_Wk
               : (z == 2) ? (uint4*)g_Wv : (z == 3) ? (uint4*)g_Wo : (uint4*)g_Xh;
    int n8 = (z == 4) ? nx8 : nw8;
    int i = (blockIdx.x * blockDim.x + threadIdx.x) * 2;
    cvt_one(src, dst, n8, i);
    cvt_one(src, dst, n8, i + 1);
}

// ===========================================================================
// fp16 mma GEMM (NT): BM=BN=128, BK=64, 8 warps (2x4), warp tile 64x32,
// 3-stage cp.async ring, one __syncthreads per K-iter, 2 CTAs/SM.
// ===========================================================================
#define ROWB 144
#define GTILE (128 * ROWB)
#define GSTG  (2 * GTILE)                     // 36864 per stage
#define GEMM_SMEM (3 * GSTG)                  // 110592 (x2 CTAs = 216KB)

__device__ __forceinline__ void gemm_stage_load(
    const __half* __restrict__ A, const __half* __restrict__ Bw, int K,
    int bm, int bn, int k0, u32 sA, u32 sB, int tid)
{
#pragma unroll
    for (int i = 0; i < 4; i++) {
        int c = tid + i * 256;
        int r = c >> 3, cb = (c & 7) << 4;
        cp16(sA + r * ROWB + cb,
             (const char*)(A + (long)(bm + r) * K + k0) + cb);
    }
#pragma unroll
    for (int i = 0; i < 4; i++) {
        int c = tid + i * 256;
        int r = c >> 3, cb = (c & 7) << 4;
        cp16(sB + r * ROWB + cb,
             (const char*)(Bw + (long)(bn + r) * K + k0) + cb);
    }
}

__device__ __forceinline__ void gemm_core(
    const __half* __restrict__ A, const __half* __restrict__ Bw,
    int bm, int bn, int K, u32 sbase, int tid,
    u32 a_off, u32 b_off, float acc[4][4][4])
{
    const int KT = K / 64;

    gemm_stage_load(A, Bw, K, bm, bn, 0, sbase, sbase + GTILE, tid);
    asm volatile("cp.async.commit_group;\n" ::: "memory");
    gemm_stage_load(A, Bw, K, bm, bn, 64, sbase + GSTG, sbase + GSTG + GTILE, tid);
    asm volatile("cp.async.commit_group;\n" ::: "memory");

    int slot = 0;
    for (int kt = 0; kt < KT; kt++) {
        asm volatile("cp.async.wait_group %0;\n" :: "n"(1) : "memory");
        __syncthreads();

        if (kt + 2 < KT) {
            int ps = slot + 2;
            if (ps >= 3) ps -= 3;
            u32 st = sbase + ps * GSTG;
            gemm_stage_load(A, Bw, K, bm, bn, (kt + 2) * 64, st, st + GTILE, tid);
        }
        asm volatile("cp.async.commit_group;\n" ::: "memory");

        u32 aB = sbase + slot * GSTG + a_off;
        u32 bB = sbase + slot * GSTG + GTILE + b_off;
#pragma unroll
        for (int ks = 0; ks < 4; ks++) {
            u32 af[4][4], bf[2][4];
#pragma unroll
            for (int mt = 0; mt < 4; mt++)
                ldmx4(aB + mt * (16 * ROWB) + ks * 32,
                      af[mt][0], af[mt][1], af[mt][2], af[mt][3]);
#pragma unroll
            for (int np = 0; np < 2; np++)
                ldmx4(bB + np * (64 * ROWB) + ks * 32,
                      bf[np][0], bf[np][1], bf[np][2], bf[np][3]);
#pragma unroll
            for (int mt = 0; mt < 4; mt++)
#pragma unroll
                for (int nt = 0; nt < 4; nt++)
                    mma_h(acc[mt][nt], af[mt], &bf[nt >> 1][(nt & 1) * 2]);
        }
        if (++slot == 3) slot = 0;
    }
}

// Fused Q/K/V projection: blockIdx.z selects weight/output; z<2 applies RoPE.
__global__ __launch_bounds__(256, 2) void gemm_qkv(const __half* __restrict__ A,
                                                   const int* __restrict__ pos) {
    extern __shared__ char smg[];
    u32 sbase = smem_u32(smg);
    int tid = threadIdx.x;
    int lane = tid & 31, wid = tid >> 5;
    int wm = wid & 1, wn = wid >> 1;
    int bm = blockIdx.y * 128;
    int bn = blockIdx.x * 128;
    int z = blockIdx.z;

    const __half* Bw = (z == 0) ? g_Wq : (z == 1) ? g_Wk : g_Wv;
    __half* C = (z == 0) ? g_Qh : (z == 1) ? g_Kh : g_Vh;

    u32 a_off = (u32)((wm * 64 + (lane & 15)) * ROWB + (lane >> 4) * 16);
    u32 b_off = (u32)((wn * 16 + (lane & 7) + ((lane & 16) ? 8 : 0)) * ROWB +
                      ((lane & 8) ? 16 : 0));

    float acc[4][4][4];
#pragma unroll
    for (int i = 0; i < 4; i++)
#pragma unroll
        for (int j = 0; j < 4; j++)
#pragma unroll
            for (int q = 0; q < 4; q++) acc[i][j][q] = 0.f;

    gemm_core(A, Bw, bm, bn, HID, sbase, tid, a_off, b_off, acc);

    int r0 = bm + wm * 64 + (lane >> 2);
    int cq0 = wn * 16 + (lane & 3) * 2;

    if (z < 2) {
        int rh = NH - 1 - blockIdx.x;            // reversed head order
        float ratio_inv = 1.0f / (1.0f + 2.0f * ((float)rh / (float)NH));
        const float L2 = 13.287712379549449f;    // log2(10000)
#pragma unroll
        for (int mt = 0; mt < 4; mt++) {
#pragma unroll
            for (int t = 0; t < 2; t++) {
                int row = r0 + mt * 16 + t * 8;
                float tp = (float)pos[row] * ratio_inv;
#pragma unroll
                for (int loc = 0; loc < 2; loc++) {
#pragma unroll
                    for (int cq = 0; cq < 2; cq++) {
                        int d = cq0 + loc * 8 + cq;
                        float inv_freq = exp2f(-((float)d * (1.0f / 64.0f)) * L2);
                        float sn, cs;
                        sincosf(tp * inv_freq, &sn, &cs);
                        int q = t * 2 + cq;
                        float a = acc[mt][loc][q];
                        float b = acc[mt][loc + 2][q];
                        acc[mt][loc][q]     = a * cs - b * sn;
                        acc[mt][loc + 2][q] = b * cs + a * sn;
                    }
                }
            }
        }
    }

#pragma unroll
    for (int mt = 0; mt < 4; mt++) {
#pragma unroll
        for (int nt = 0; nt < 4; nt++) {
            long r = r0 + mt * 16;
            int c = bn + cq0 + (nt & 1) * 8 + (nt >> 1) * 64;
            *(u32*)((char*)C + (r * HID + c) * 2) =
                pack_h2(acc[mt][nt][0], acc[mt][nt][1]);
            *(u32*)((char*)C + ((r + 8) * HID + c) * 2) =
                pack_h2(acc[mt][nt][2], acc[mt][nt][3]);
        }
    }
}

// Output projection: fp32 out.
__global__ __launch_bounds__(256, 2) void gemm_o(const __half* __restrict__ A,
                                                 float* __restrict__ C) {
    extern __shared__ char smg[];
    u32 sbase = smem_u32(smg);
    int tid = threadIdx.x;
    int lane = tid & 31, wid = tid >> 5;
    int wm = wid & 1, wn = wid >> 1;
    int bm = blockIdx.y * 128;
    int bn = blockIdx.x * 128;

    u32 a_off = (u32)((wm * 64 + (lane & 15)) * ROWB + (lane >> 4) * 16);
    u32 b_off = (u32)((wn * 16 + (lane & 7) + ((lane & 16) ? 8 : 0)) * ROWB +
                      ((lane & 8) ? 16 : 0));

    float acc[4][4][4];
#pragma unroll
    for (int i = 0; i < 4; i++)
#pragma unroll
        for (int j = 0; j < 4; j++)
#pragma unroll
            for (int q = 0; q < 4; q++) acc[i][j][q] = 0.f;

    gemm_core(A, g_Wo, bm, bn, HID, sbase, tid, a_off, b_off, acc);

    int r0 = bm + wm * 64 + (lane >> 2);
    int cq0 = wn * 16 + (lane & 3) * 2;
#pragma unroll
    for (int mt = 0; mt < 4; mt++) {
#pragma unroll
        for (int nt = 0; nt < 4; nt++) {
            long r = r0 + mt * 16;
            int c = bn + cq0 + (nt & 1) * 8 + (nt >> 1) * 64;
            *(float2*)&C[r * HID + c] =
                make_float2(acc[mt][nt][0], acc[mt][nt][1]);
            *(float2*)&C[(r + 8) * HID + c] =
                make_float2(acc[mt][nt][2], acc[mt][nt][3]);
        }
    }
}

// ===========================================================================
// fp16 tensor-core causal flash attention. BQ=64, BKV=64, D=128, 128 thr,
// 3 CTAs/SM, Q fragments from global (no Q smem), grid (head, tile) big-first.
// ===========================================================================
#define FROWB 272
#define FTILE (64 * FROWB)                     // 17408
#define FSTG (2 * FTILE)                       // K + V per stage
#define FLASH_SMEM (2 * FSTG)                  // 69632 (x3 CTAs = 209KB)

__global__ __launch_bounds__(128, 3) void flash_h() {
    extern __shared__ char smf[];
    u32 sbase = smem_u32(smf);
    int tid = threadIdx.x;
    int lane = tid & 31, wid = tid >> 5;       // 4 warps
    int h = blockIdx.x;                        // head (x-fastest)
    int qt = 31 - blockIdx.y;                  // big tiles first across heads
    int q0 = qt * 64;
    int nk = qt + 1;

    // KV stage 0
    {
        u32 kb = sbase, vb = sbase + FTILE;
#pragma unroll
        for (int i = 0; i < 8; i++) {
            int c = tid + i * 128;
            int r = c >> 4, cb = (c & 15) << 4;
            long gb = (long)r * HID + h * HD;
            cp16(kb + r * FROWB + cb, (const char*)(g_Kh + gb) + cb);
            cp16(vb + r * FROWB + cb, (const char*)(g_Vh + gb) + cb);
        }
    }
    asm volatile("cp.async.commit_group;\n" ::: "memory");

    // Q fragments straight from global in mma A layout:
    // aq[d8][j] = Q[q0 + wid*16 + (lane>>2) + (j&1)*8][d8*16 + (lane&3)*2 + (j>>1)*8]
    u32 aq[8][4];
    {
        const __half* qb = g_Qh + (long)(q0 + wid * 16 + (lane >> 2)) * HID
                         + h * HD + (lane & 3) * 2;
#pragma unroll
        for (int d8 = 0; d8 < 8; d8++)
#pragma unroll
            for (int j = 0; j < 4; j++)
                aq[d8][j] = *(const u32*)(qb + (long)(j & 1) * 8 * HID
                                             + d8 * 16 + (j >> 1) * 8);
    }

    float o[16][4];
    float m[2] = {-INFINITY, -INFINITY};
    float l[2] = {0.f, 0.f};
#pragma unroll
    for (int nt = 0; nt < 16; nt++)
#pragma unroll
        for (int q = 0; q < 4; q++) o[nt][q] = 0.f;

    const float SC = 0.1275174461600732f;      // 1/sqrt(128) * log2(e)
    u32 k_off = (u32)(((lane & 7) + ((lane & 16) ? 8 : 0)) * FROWB +
                      ((lane & 8) ? 16 : 0));
    u32 v_off = (u32)(((lane & 7) + ((lane & 8) ? 8 : 0)) * FROWB +
                      ((lane & 16) ? 16 : 0));

    for (int kt = 0; kt < nk; kt++) {
        int k0 = kt * 64;
        asm volatile("cp.async.wait_group 0;\n" ::: "memory");
        __syncthreads();

        if (kt + 1 < nk) {
            u32 kb = sbase + ((kt + 1) & 1) * FSTG;
            u32 vb = kb + FTILE;
            long krow = (long)(kt + 1) * 64;
#pragma unroll
            for (int i = 0; i < 8; i++) {
                int c = tid + i * 128;
                int r = c >> 4, cb = (c & 15) << 4;
                long gb = (krow + r) * HID + h * HD;
                cp16(kb + r * FROWB + cb, (const char*)(g_Kh + gb) + cb);
                cp16(vb + r * FROWB + cb, (const char*)(g_Vh + gb) + cb);
            }
            asm volatile("cp.async.commit_group;\n" ::: "memory");
        }

        u32 kbase = sbase + (kt & 1) * FSTG;
        u32 vbase = kbase + FTILE;

        float c[8][4];
#pragma unroll
        for (int j = 0; j < 8; j++)
#pragma unroll
            for (int q = 0; q < 4; q++) c[j][q] = 0.f;

#pragma unroll
        for (int d8 = 0; d8 < 8; d8++) {
            u32 bf[4][4];
#pragma unroll
            for (int np = 0; np < 4; np++)
                ldmx4(kbase + k_off + np * (16 * FROWB) + d8 * 32,
                      bf[np][0], bf[np][1], bf[np][2], bf[np][3]);
#pragma unroll
            for (int np = 0; np < 4; np++) {
                mma_h(c[2 * np],     aq[d8], &bf[np][0]);
                mma_h(c[2 * np + 1], aq[d8], &bf[np][2]);
            }
        }

#pragma unroll
        for (int j = 0; j < 8; j++)
#pragma unroll
            for (int q = 0; q < 4; q++) c[j][q] *= SC;

        if (k0 + 63 > q0 + wid * 16) {
            int rbase = q0 + wid * 16 + (lane >> 2);
#pragma unroll
            for (int j = 0; j < 8; j++) {
                int col = k0 + j * 8 + (lane & 3) * 2;
#pragma unroll
                for (int t = 0; t < 2; t++) {
                    int row = rbase + t * 8;
                    if (col > row)     c[j][2 * t]     = -INFINITY;
                    if (col + 1 > row) c[j][2 * t + 1] = -INFINITY;
                }
            }
        }

#pragma unroll
        for (int t = 0; t < 2; t++) {
            float mx = -INFINITY;
#pragma unroll
            for (int j = 0; j < 8; j++)
                mx = fmaxf(mx, fmaxf(c[j][2 * t], c[j][2 * t + 1]));
            mx = fmaxf(mx, __shfl_xor_sync(0xffffffffu, mx, 1));
            mx = fmaxf(mx, __shfl_xor_sync(0xffffffffu, mx, 2));
            float mnew = fmaxf(m[t], mx);
            float corr = exp2f(m[t] - mnew);
            float rs = 0.f;
#pragma unroll
            for (int j = 0; j < 8; j++) {
                float p0 = exp2f(c[j][2 * t] - mnew);
                float p1 = exp2f(c[j][2 * t + 1] - mnew);
                c[j][2 * t] = p0;
                c[j][2 * t + 1] = p1;
                rs += p0 + p1;
            }
            rs += __shfl_xor_sync(0xffffffffu, rs, 1);
            rs += __shfl_xor_sync(0xffffffffu, rs, 2);
            l[t] = l[t] * corr + rs;
            m[t] = mnew;
#pragma unroll
            for (int nt = 0; nt < 16; nt++) {
                o[nt][2 * t] *= corr;
                o[nt][2 * t + 1] *= corr;
            }
        }

        u32 ph[4][4];
#pragma unroll
        for (int t = 0; t < 4; t++) {
            ph[t][0] = pack_h2(c[2 * t][0], c[2 * t][1]);
            ph[t][1] = pack_h2(c[2 * t][2], c[2 * t][3]);
            ph[t][2] = pack_h2(c[2 * t + 1][0], c[2 * t + 1][1]);
            ph[t][3] = pack_h2(c[2 * t + 1][2], c[2 * t + 1][3]);
        }

#pragma unroll
        for (int t = 0; t < 4; t++) {
            u32 vrow = vbase + v_off + t * (16 * FROWB);
#pragma unroll
            for (int np = 0; np < 8; np++) {
                u32 b0, b1, b2, b3;
                ldmx4t(vrow + np * 32, b0, b1, b2, b3);
                u32 bl[2] = {b0, b1};
                u32 bh[2] = {b2, b3};
                mma_h(o[2 * np], ph[t], bl);
                mma_h(o[2 * np + 1], ph[t], bh);
            }
        }
    }

    float inv0 = 1.0f / l[0], inv1 = 1.0f / l[1];
    long row = q0 + wid * 16 + (lane >> 2);
    int colb = h * HD + (lane & 3) * 2;
#pragma unroll
    for (int nt = 0; nt < 16; nt++) {
        int c = colb + nt * 8;
        *(u32*)((char*)g_Ah + (row * HID + c) * 2) =
            pack_h2(o[nt][0] * inv0, o[nt][1] * inv0);
        *(u32*)((char*)g_Ah + ((row + 8) * HID + c) * 2) =
            pack_h2(o[nt][2] * inv1, o[nt][3] * inv1);
    }
}

// ---------------------------------------------------------------------------
extern "C" void kernel_launch(void* const* d_in, const int* in_sizes, int n_in,
                              void* d_out, int out_size) {
    (void)in_sizes; (void)n_in; (void)out_size;
    const float* x   = (const float*)d_in[0];
    const int*   pos = (const int*)d_in[1];
    const float* wq  = (const float*)d_in[2];
    const float* wk  = (const float*)d_in[3];
    const float* wv  = (const float*)d_in[4];
    const float* wo  = (const float*)d_in[5];
    float* out = (float*)d_out;

    __half *Xh, *Ah;
    cudaGetSymbolAddress((void**)&Xh, g_Xh);
    cudaGetSymbolAddress((void**)&Ah, g_Ah);

    {
        int nx8 = SEQ * HID / 8;
        int nw8 = HID * HID / 8;
        int bw = (nw8 / 2 + 255) / 256;
        cvt_all<<<dim3(bw, 5), 256>>>((const float4*)wq, (const float4*)wk,
                                      (const float4*)wv, (const float4*)wo,
                                      (const float4*)x, nw8, nx8);
    }

    cudaFuncSetAttribute(gemm_qkv,
                         cudaFuncAttributeMaxDynamicSharedMemorySize, GEMM_SMEM);
    cudaFuncSetAttribute(gemm_o,
                         cudaFuncAttributeMaxDynamicSharedMemorySize, GEMM_SMEM);
    cudaFuncSetAttribute(flash_h,
                         cudaFuncAttributeMaxDynamicSharedMemorySize, FLASH_SMEM);

    gemm_qkv<<<dim3(32, 16, 3), 256, GEMM_SMEM>>>(Xh, pos);

    flash_h<<<dim3(32, 32), 128, FLASH_SMEM>>>();

    gemm_o<<<dim3(32, 16), 256, GEMM_SMEM>>>(Ah, out);
}